// round 16
// baseline (speedup 1.0000x reference)
#include <cuda_runtime.h>
#include <math.h>

// Normalized W lives here: 2 rows x 512 cols
__device__ float g_Wn[2 * 512];

static constexpr float EPS_CLIP = 1e-7f;
static constexpr float SCALE    = 64.0f;
// cos(0.5), sin(0.5)
static constexpr float COS_M = 0.8775825618903728f;
static constexpr float SIN_M = 0.479425538604203f;

// Rows per concurrent wave: 148 SMs x 8 blocks/SM x 8 rows/block.
static constexpr int PREF_DIST_ROWS = 148 * 8 * 8;   // 9472 rows ~= 19 MB

// ---------------------------------------------------------------------------
// Prologue: L2-normalize W rows (C=2, D=512) into g_Wn. Fires PDL so the
// main grid launches immediately and overlaps this kernel.
// ---------------------------------------------------------------------------
__global__ void normalize_w_kernel(const float* __restrict__ W) {
    asm volatile("griddepcontrol.launch_dependents;" ::: "memory");

    const int row = blockIdx.x;            // 0 or 1
    const int tid = threadIdx.x;           // 0..127
    const float* wrow = W + row * 512;

    float ss = 0.0f;
    #pragma unroll
    for (int i = tid; i < 512; i += 128) {
        float v = wrow[i];
        ss += v * v;
    }
    #pragma unroll
    for (int o = 16; o > 0; o >>= 1) ss += __shfl_xor_sync(0xffffffff, ss, o);

    __shared__ float warp_ss[4];
    __shared__ float s_inv;
    const int lane = tid & 31;
    const int wid  = tid >> 5;
    if (lane == 0) warp_ss[wid] = ss;
    __syncthreads();
    if (tid == 0) {
        float tot = warp_ss[0] + warp_ss[1] + warp_ss[2] + warp_ss[3];
        s_inv = 1.0f / fmaxf(sqrtf(tot), 1e-12f);
    }
    __syncthreads();

    const float inv = s_inv;
    #pragma unroll
    for (int i = tid; i < 512; i += 128) {
        g_Wn[row * 512 + i] = wrow[i] * inv;
    }
}

// ---------------------------------------------------------------------------
// Main: R10 body byte-for-byte (one warp per row, feat loads before the
// PDL wait — the wait doubles as the scheduling fence that keeps the feat
// load batch front-issued), plus ONE addition: an L2 prefetch of the row
// one wave ahead, issued inside the load batch. Next wave's demand loads
// hit L2 instead of DRAM, keeping DRAM streaming through the per-warp
// reduce/epilogue dead windows.
// ---------------------------------------------------------------------------
__global__ void __launch_bounds__(256, 8)
arcface_kernel(const float* __restrict__ feat,
               const int*   __restrict__ label,
               float*       __restrict__ out,
               int B)
{
    const int row  = (blockIdx.x * blockDim.x + threadIdx.x) >> 5;
    const int lane = threadIdx.x & 31;
    if (row >= B) return;

    const float4* __restrict__ f =
        reinterpret_cast<const float4*>(feat + (size_t)row * 512);

    // Issue the 4 streaming feat loads first — overlap with prologue.
    float4 a0 = f[lane];
    float4 a1 = f[lane + 32];
    float4 a2 = f[lane + 64];
    float4 a3 = f[lane + 96];

    // Prefetch the row one wave ahead into L2 (32 lanes x 64B = 2KB row).
    if (row + PREF_DIST_ROWS < B) {
        const char* p = reinterpret_cast<const char*>(feat)
                      + (size_t)(row + PREF_DIST_ROWS) * 2048 + lane * 64;
        asm volatile("prefetch.global.L2 [%0];" :: "l"(p));
    }

    // Wait for normalize_w_kernel to complete (its g_Wn writes visible).
    asm volatile("griddepcontrol.wait;" ::: "memory");

    const float4* __restrict__ w0 = reinterpret_cast<const float4*>(g_Wn);
    const float4* __restrict__ w1 = reinterpret_cast<const float4*>(g_Wn + 512);

    float ss = 0.0f, d0 = 0.0f, d1 = 0.0f;

    {
        float4 b, c;
        #define ACC(A, K)                                                     \
            b = w0[lane + 32 * (K)];                                          \
            c = w1[lane + 32 * (K)];                                          \
            ss = fmaf(A.x, A.x, ss); ss = fmaf(A.y, A.y, ss);                 \
            ss = fmaf(A.z, A.z, ss); ss = fmaf(A.w, A.w, ss);                 \
            d0 = fmaf(A.x, b.x, d0); d0 = fmaf(A.y, b.y, d0);                 \
            d0 = fmaf(A.z, b.z, d0); d0 = fmaf(A.w, b.w, d0);                 \
            d1 = fmaf(A.x, c.x, d1); d1 = fmaf(A.y, c.y, d1);                 \
            d1 = fmaf(A.z, c.z, d1); d1 = fmaf(A.w, c.w, d1);
        ACC(a0, 0)
        ACC(a1, 1)
        ACC(a2, 2)
        ACC(a3, 3)
        #undef ACC
    }

    #pragma unroll
    for (int o = 16; o > 0; o >>= 1) {
        ss += __shfl_xor_sync(0xffffffff, ss, o);
        d0 += __shfl_xor_sync(0xffffffff, d0, o);
        d1 += __shfl_xor_sync(0xffffffff, d1, o);
    }

    if (lane == 0) {
        const float invf = rsqrtf(fmaxf(ss, 1e-24f));

        float c0 = fminf(fmaxf(d0 * invf, -1.0f + EPS_CLIP), 1.0f - EPS_CLIP);
        float c1 = fminf(fmaxf(d1 * invf, -1.0f + EPS_CLIP), 1.0f - EPS_CLIP);

        // cos(theta + m) = cos*cos_m - sin*sin_m, sin = sqrt(1-cos^2) >= 0
        float s0 = sqrtf(fmaxf(1.0f - c0 * c0, 0.0f));
        float s1 = sqrtf(fmaxf(1.0f - c1 * c1, 0.0f));
        float m0 = c0 * COS_M - s0 * SIN_M;
        float m1 = c1 * COS_M - s1 * SIN_M;

        const int lab = label[row];
        float o0 = (lab == 0) ? m0 : c0;
        float o1 = (lab == 1) ? m1 : c1;

        reinterpret_cast<float2*>(out)[row] = make_float2(o0 * SCALE, o1 * SCALE);
    }
}

// ---------------------------------------------------------------------------
// kernel_launch: identify inputs by element count (robust to ordering):
//   feat : B*D f32 (largest), W : C*D f32 (smallest), label : B int32
// PDL launch for the main kernel.
// ---------------------------------------------------------------------------
extern "C" void kernel_launch(void* const* d_in, const int* in_sizes, int n_in,
                              void* d_out, int out_size)
{
    int i_feat = 0, i_w = 0, i_lab = 0;
    for (int i = 1; i < n_in; i++) {
        if (in_sizes[i] > in_sizes[i_feat]) i_feat = i;
        if (in_sizes[i] < in_sizes[i_w])    i_w    = i;
    }
    for (int i = 0; i < n_in; i++)
        if (i != i_feat && i != i_w) i_lab = i;

    const float* feat  = (const float*)d_in[i_feat];
    const float* W     = (const float*)d_in[i_w];
    const int*   label = (const int*)d_in[i_lab];
    float*       out   = (float*)d_out;
    const int    B     = in_sizes[i_lab];

    normalize_w_kernel<<<2, 128>>>(W);

    const int blocks = (B + 7) / 8;        // 8 rows (warps) per block

    cudaLaunchConfig_t cfg = {};
    cfg.gridDim  = dim3((unsigned)blocks, 1, 1);
    cfg.blockDim = dim3(256, 1, 1);
    cfg.dynamicSmemBytes = 0;
    cfg.stream = 0;

    cudaLaunchAttribute attr[1];
    attr[0].id = cudaLaunchAttributeProgrammaticStreamSerialization;
    attr[0].val.programmaticStreamSerializationAllowed = 1;
    cfg.attrs = attr;
    cfg.numAttrs = 1;

    cudaLaunchKernelEx(&cfg, arcface_kernel, feat, label, out, B);
}

// round 17
// speedup vs baseline: 1.5427x; 1.5427x over previous
#include <cuda_runtime.h>
#include <math.h>

// Inverse L2 norms of the two W rows (written by prologue, 8 bytes).
__device__ float g_invw[2];

static constexpr float EPS_CLIP = 1e-7f;
static constexpr float SCALE    = 64.0f;
// cos(0.5), sin(0.5)
static constexpr float COS_M = 0.8775825618903728f;
static constexpr float SIN_M = 0.479425538604203f;

// ---------------------------------------------------------------------------
// Slim prologue: ONE block, 2 warps, one W row per warp; computes only the
// two inverse norms (8 B output, no 4 KB write-back). Fires PDL immediately.
// ---------------------------------------------------------------------------
__global__ void wnorm_kernel(const float* __restrict__ W) {
    asm volatile("griddepcontrol.launch_dependents;" ::: "memory");

    const int wid  = threadIdx.x >> 5;     // 0 or 1 -> W row
    const int lane = threadIdx.x & 31;

    const float4* __restrict__ w =
        reinterpret_cast<const float4*>(W + wid * 512);

    float ss = 0.0f;
    #pragma unroll
    for (int k = 0; k < 4; k++) {
        float4 v = w[lane + 32 * k];
        ss = fmaf(v.x, v.x, ss); ss = fmaf(v.y, v.y, ss);
        ss = fmaf(v.z, v.z, ss); ss = fmaf(v.w, v.w, ss);
    }
    #pragma unroll
    for (int o = 16; o > 0; o >>= 1) ss += __shfl_xor_sync(0xffffffff, ss, o);

    if (lane == 0) g_invw[wid] = rsqrtf(fmaxf(ss, 1e-24f));
}

// ---------------------------------------------------------------------------
// Main: R10 body with identical instruction schedule — one warp per row,
// 4 front-batched feat LDG.128, griddepcontrol.wait in the SAME position
// (between feat and W loads; doubles as the scheduling fence), 8 W LDG.128
// (raw W, L1 hits), 48 FMA, 3-chain SHFL reduce. Epilogue folds the two
// scalar inverse W norms (g_invw) into the cosines.
// ---------------------------------------------------------------------------
__global__ void __launch_bounds__(256, 8)
arcface_kernel(const float* __restrict__ feat,
               const float* __restrict__ W,
               const int*   __restrict__ label,
               float*       __restrict__ out,
               int B)
{
    const int row  = (blockIdx.x * blockDim.x + threadIdx.x) >> 5;
    const int lane = threadIdx.x & 31;
    if (row >= B) return;

    const float4* __restrict__ f =
        reinterpret_cast<const float4*>(feat + (size_t)row * 512);

    // Issue the 4 streaming feat loads first — overlap with prologue.
    float4 a0 = f[lane];
    float4 a1 = f[lane + 32];
    float4 a2 = f[lane + 64];
    float4 a3 = f[lane + 96];

    // Wait for wnorm_kernel (also acts as the load-scheduling fence).
    asm volatile("griddepcontrol.wait;" ::: "memory");

    const float4* __restrict__ w0 = reinterpret_cast<const float4*>(W);
    const float4* __restrict__ w1 = reinterpret_cast<const float4*>(W + 512);

    float ss = 0.0f, d0 = 0.0f, d1 = 0.0f;

    {
        float4 b, c;
        #define ACC(A, K)                                                     \
            b = w0[lane + 32 * (K)];                                          \
            c = w1[lane + 32 * (K)];                                          \
            ss = fmaf(A.x, A.x, ss); ss = fmaf(A.y, A.y, ss);                 \
            ss = fmaf(A.z, A.z, ss); ss = fmaf(A.w, A.w, ss);                 \
            d0 = fmaf(A.x, b.x, d0); d0 = fmaf(A.y, b.y, d0);                 \
            d0 = fmaf(A.z, b.z, d0); d0 = fmaf(A.w, b.w, d0);                 \
            d1 = fmaf(A.x, c.x, d1); d1 = fmaf(A.y, c.y, d1);                 \
            d1 = fmaf(A.z, c.z, d1); d1 = fmaf(A.w, c.w, d1);
        ACC(a0, 0)
        ACC(a1, 1)
        ACC(a2, 2)
        ACC(a3, 3)
        #undef ACC
    }

    #pragma unroll
    for (int o = 16; o > 0; o >>= 1) {
        ss += __shfl_xor_sync(0xffffffff, ss, o);
        d0 += __shfl_xor_sync(0xffffffff, d0, o);
        d1 += __shfl_xor_sync(0xffffffff, d1, o);
    }

    if (lane == 0) {
        const float invf = rsqrtf(fmaxf(ss, 1e-24f));

        float c0 = fminf(fmaxf(d0 * invf * g_invw[0], -1.0f + EPS_CLIP), 1.0f - EPS_CLIP);
        float c1 = fminf(fmaxf(d1 * invf * g_invw[1], -1.0f + EPS_CLIP), 1.0f - EPS_CLIP);

        // cos(theta + m) = cos*cos_m - sin*sin_m, sin = sqrt(1-cos^2) >= 0
        float s0 = sqrtf(fmaxf(1.0f - c0 * c0, 0.0f));
        float s1 = sqrtf(fmaxf(1.0f - c1 * c1, 0.0f));
        float m0 = c0 * COS_M - s0 * SIN_M;
        float m1 = c1 * COS_M - s1 * SIN_M;

        const int lab = label[row];
        float o0 = (lab == 0) ? m0 : c0;
        float o1 = (lab == 1) ? m1 : c1;

        reinterpret_cast<float2*>(out)[row] = make_float2(o0 * SCALE, o1 * SCALE);
    }
}

// ---------------------------------------------------------------------------
// kernel_launch: identify inputs by element count (robust to ordering):
//   feat : B*D f32 (largest), W : C*D f32 (smallest), label : B int32
// PDL launch for the main kernel.
// ---------------------------------------------------------------------------
extern "C" void kernel_launch(void* const* d_in, const int* in_sizes, int n_in,
                              void* d_out, int out_size)
{
    int i_feat = 0, i_w = 0, i_lab = 0;
    for (int i = 1; i < n_in; i++) {
        if (in_sizes[i] > in_sizes[i_feat]) i_feat = i;
        if (in_sizes[i] < in_sizes[i_w])    i_w    = i;
    }
    for (int i = 0; i < n_in; i++)
        if (i != i_feat && i != i_w) i_lab = i;

    const float* feat  = (const float*)d_in[i_feat];
    const float* W     = (const float*)d_in[i_w];
    const int*   label = (const int*)d_in[i_lab];
    float*       out   = (float*)d_out;
    const int    B     = in_sizes[i_lab];

    wnorm_kernel<<<1, 64>>>(W);

    const int blocks = (B + 7) / 8;        // 8 rows (warps) per block

    cudaLaunchConfig_t cfg = {};
    cfg.gridDim  = dim3((unsigned)blocks, 1, 1);
    cfg.blockDim = dim3(256, 1, 1);
    cfg.dynamicSmemBytes = 0;
    cfg.stream = 0;

    cudaLaunchAttribute attr[1];
    attr[0].id = cudaLaunchAttributeProgrammaticStreamSerialization;
    attr[0].val.programmaticStreamSerializationAllowed = 1;
    cfg.attrs = attr;
    cfg.numAttrs = 1;

    cudaLaunchKernelEx(&cfg, arcface_kernel, feat, W, label, out, B);
}